// round 14
// baseline (speedup 1.0000x reference)
#include <cuda_runtime.h>

#define PP 8
#define BB 256
#define NN 512
#define KK 64
#define THREADS 256

// n = N*rho^2 = 510.976512 ; g = 0.5*(log(1+rho)-log(1-rho))/rho
#define G_CONST  3.8040054350965846f
#define INV_N    0.00195703687008f

__device__ __forceinline__ void l2_prefetch(const void* p, unsigned bytes) {
    asm volatile("cp.async.bulk.prefetch.L2.global [%0], %1;"
                 :: "l"(p), "r"(bytes) : "memory");
}

__global__ __launch_bounds__(THREADS, 4)
void ghu_kernel(const float* __restrict__ WL,
                const float* __restrict__ WR,
                const float* __restrict__ v_tm1,
                const float* __restrict__ v_t,
                const int*   __restrict__ ac_idx,
                const int*   __restrict__ pc_mask,
                float* __restrict__ out) {
    const int b = blockIdx.x;
    const int p = blockIdx.y;
    const int tid  = threadIdx.x;
    const int warp = tid >> 5;
    const int lane = tid & 31;

    const bool sel = (ac_idx[b] == p);
    const bool msk = (pc_mask[b * PP + p] != 0);

    float* out_vnext = out;                                    // [B,N]
    float* out_dWL   = out + (size_t)BB * NN;                  // [P,B,N,1]
    float* out_dWR   = out_dWL + (size_t)PP * BB * NN;         // [P,B,1,N]
    float* dWLrow = out_dWL + ((size_t)p * BB + b) * NN;
    float* dWRrow = out_dWR + ((size_t)p * BB + b) * NN;
    const float* vtm1_row = v_tm1 + (size_t)b * NN;
    const float* vt_row   = v_t   + (size_t)b * NN;

    const size_t tileOff = ((size_t)p * BB + b) * (size_t)(NN * KK);
    const float* WRt = WR + tileOff;   // [K, N], N contiguous
    const float* WLt = WL + tileOff;   // [N, K], K contiguous

    // WL-only DRAM->L2 prefetch for heavy blocks: WL is consumed in phase B,
    // ~2-3us after block start. Live prefetch footprint: resident heavy
    // blocks x 128 KB ~= 74 MB < 126 MB L2 (both-tiles variant thrashed).
    if ((msk || sel) && tid == 0)
        l2_prefetch(WLt, NN * KK * 4u);

    // ---- dWR needs no weight data: vectorized write (128 float4) ----
    if (tid < NN / 4) {
        float4 vv = ((const float4*)vtm1_row)[tid];
        float4 o;
        if (msk) { o.x = vv.x * INV_N; o.y = vv.y * INV_N;
                   o.z = vv.z * INV_N; o.w = vv.w * INV_N; }
        else     { o = make_float4(0.f, 0.f, 0.f, 0.f); }
        ((float4*)dWRrow)[tid] = o;
    }

    // Light tiles: zero dWL, done. No weight reads.
    if (!msk && !sel) {
        if (tid < NN / 4)
            ((float4*)dWLrow)[tid] = make_float4(0.f, 0.f, 0.f, 0.f);
        return;
    }

    __shared__ __align__(16) float svA[NN];     // dot vector (v_tm1 or v_t)
    __shared__ __align__(16) float svB[NN];     // second vector (full path only)
    __shared__ __align__(16) float sWRx[KK];
    __shared__ __align__(16) float sWx[KK];
    __shared__ __align__(16) float sAcc1[NN];
    __shared__ __align__(16) float sAcc2[NN];

    if (msk != sel) {
        // ================= SINGLE-DOT PATH (~90% of heavy tiles) ==========
        // Only one matvec chain is consumed: dot vector is v_tm1 when msk
        // (rank-1 growth), v_t when sel (tick update). One accumulator set
        // frees registers -> 8-row batches (MLP 8), half the shuffles.
        const float* vrow = msk ? vtm1_row : vt_row;
        if (tid < NN / 4)
            ((float4*)svA)[tid] = ((const float4*)vrow)[tid];
        __syncthreads();

        // ---- Phase A: warp w owns WR k-rows [8w .. 8w+7], one batch ----
        {
            const float* base = WRt + (size_t)(8 * warp) * NN;
            float acc[8] = {0.f,0.f,0.f,0.f,0.f,0.f,0.f,0.f};
            #pragma unroll
            for (int j = 0; j < 4; j++) {
                const int idx = lane + 32 * j;
                const int vb  = 4 * idx;
                float4 w[8];
                #pragma unroll
                for (int r = 0; r < 8; r++)
                    w[r] = ((const float4*)(base + r * NN))[idx];
                const float u0 = svA[vb + 0], u1 = svA[vb + 1];
                const float u2 = svA[vb + 2], u3 = svA[vb + 3];
                #pragma unroll
                for (int r = 0; r < 8; r++)
                    acc[r] = fmaf(w[r].x, u0, fmaf(w[r].y, u1,
                             fmaf(w[r].z, u2, fmaf(w[r].w, u3, acc[r]))));
            }
            #pragma unroll
            for (int o = 16; o > 0; o >>= 1)
                #pragma unroll
                for (int r = 0; r < 8; r++)
                    acc[r] += __shfl_xor_sync(0xFFFFFFFFu, acc[r], o);
            if (lane == 0)
                #pragma unroll
                for (int r = 0; r < 8; r++)
                    sWRx[8 * warp + r] = acc[r];
        }
        __syncthreads();

        // ---- Phase B: 16-lane group g owns WL rows n = g + 16m ----
        {
            const int g  = tid >> 4;
            const int hl = tid & 15;
            const float4 s1 = ((const float4*)sWRx)[hl];
            const float4* lb = (const float4*)(WLt + (size_t)g * KK) + hl;
            #pragma unroll
            for (int bt = 0; bt < 4; bt++) {
                float4 w[8];
                #pragma unroll
                for (int r = 0; r < 8; r++)
                    w[r] = lb[(8 * bt + r) * 256];   // 16*KK floats apart
                float a[8];
                #pragma unroll
                for (int r = 0; r < 8; r++)
                    a[r] = w[r].x*s1.x + w[r].y*s1.y + w[r].z*s1.z + w[r].w*s1.w;
                #pragma unroll
                for (int o = 8; o > 0; o >>= 1)
                    #pragma unroll
                    for (int r = 0; r < 8; r++)
                        a[r] += __shfl_xor_sync(0xFFFFFFFFu, a[r], o, 16);
                if (hl == 0)
                    #pragma unroll
                    for (int r = 0; r < 8; r++)
                        sAcc1[g + 16 * (8 * bt + r)] = a[r];
            }
        }
        __syncthreads();

        // ---- Epilogue ----
        if (msk) {
            // dWL = g*v_t - WLWRx ; v_next not written (not selected)
            if (tid < 128) {
                float4 a = ((const float4*)sAcc1)[tid];
                float4 t = ((const float4*)vt_row)[tid];
                float4 o;
                o.x = G_CONST * t.x - a.x;
                o.y = G_CONST * t.y - a.y;
                o.z = G_CONST * t.z - a.z;
                o.w = G_CONST * t.w - a.w;
                ((float4*)dWLrow)[tid] = o;
            }
        } else {
            // sel only: dWL = 0 ; v_next = tanh(acc)
            if (tid < 128) {
                ((float4*)dWLrow)[tid] = make_float4(0.f, 0.f, 0.f, 0.f);
            } else {
                const int i = tid - 128;
                float4 a = ((const float4*)sAcc1)[i];
                float4 o;
                o.x = tanhf(a.x); o.y = tanhf(a.y);
                o.z = tanhf(a.z); o.w = tanhf(a.w);
                ((float4*)(out_vnext + (size_t)b * NN))[i] = o;
            }
        }
        return;
    }

    // ================= FULL DUAL-DOT PATH (msk && sel, ~6%) ===============
    if (tid < NN / 4) {
        ((float4*)svB)[tid] = ((const float4*)vt_row)[tid];
        ((float4*)svA)[tid] = ((const float4*)vtm1_row)[tid];
    }
    __syncthreads();

    // ---- Phase A: warp handles k = warp + 8*r, 4 rows per pass, 2 passes.
    #pragma unroll
    for (int rb = 0; rb < 2; rb++) {
        float a1[4] = {0.f, 0.f, 0.f, 0.f};
        float a2[4] = {0.f, 0.f, 0.f, 0.f};
        const float4* r0 = (const float4*)(WRt + (size_t)(warp + 8 * (4 * rb + 0)) * NN);
        const float4* r1 = (const float4*)(WRt + (size_t)(warp + 8 * (4 * rb + 1)) * NN);
        const float4* r2 = (const float4*)(WRt + (size_t)(warp + 8 * (4 * rb + 2)) * NN);
        const float4* r3 = (const float4*)(WRt + (size_t)(warp + 8 * (4 * rb + 3)) * NN);
        #pragma unroll
        for (int j = 0; j < 4; j++) {
            const int idx  = lane + 32 * j;
            const int base = 4 * idx;
            float4 w0 = r0[idx];
            float4 w1 = r1[idx];
            float4 w2 = r2[idx];
            float4 w3 = r3[idx];
            float u0 = svA[base + 0], u1 = svA[base + 1];
            float u2 = svA[base + 2], u3 = svA[base + 3];
            float t0 = svB[base + 0], t1 = svB[base + 1];
            float t2 = svB[base + 2], t3 = svB[base + 3];
            a1[0] = fmaf(w0.x,u0,fmaf(w0.y,u1,fmaf(w0.z,u2,fmaf(w0.w,u3,a1[0]))));
            a1[1] = fmaf(w1.x,u0,fmaf(w1.y,u1,fmaf(w1.z,u2,fmaf(w1.w,u3,a1[1]))));
            a1[2] = fmaf(w2.x,u0,fmaf(w2.y,u1,fmaf(w2.z,u2,fmaf(w2.w,u3,a1[2]))));
            a1[3] = fmaf(w3.x,u0,fmaf(w3.y,u1,fmaf(w3.z,u2,fmaf(w3.w,u3,a1[3]))));
            a2[0] = fmaf(w0.x,t0,fmaf(w0.y,t1,fmaf(w0.z,t2,fmaf(w0.w,t3,a2[0]))));
            a2[1] = fmaf(w1.x,t0,fmaf(w1.y,t1,fmaf(w1.z,t2,fmaf(w1.w,t3,a2[1]))));
            a2[2] = fmaf(w2.x,t0,fmaf(w2.y,t1,fmaf(w2.z,t2,fmaf(w2.w,t3,a2[2]))));
            a2[3] = fmaf(w3.x,t0,fmaf(w3.y,t1,fmaf(w3.z,t2,fmaf(w3.w,t3,a2[3]))));
        }
        #pragma unroll
        for (int o = 16; o > 0; o >>= 1) {
            #pragma unroll
            for (int r = 0; r < 4; r++) {
                a1[r] += __shfl_xor_sync(0xFFFFFFFFu, a1[r], o);
                a2[r] += __shfl_xor_sync(0xFFFFFFFFu, a2[r], o);
            }
        }
        if (lane == 0) {
            #pragma unroll
            for (int r = 0; r < 4; r++) {
                sWRx[warp + 8 * (4 * rb + r)] = a1[r];
                sWx [warp + 8 * (4 * rb + r)] = a2[r];
            }
        }
    }
    __syncthreads();

    // ---- Phase B: 16-lane group g owns rows n = g + 16*m, 4 rows per pass.
    {
        const int g  = tid >> 4;
        const int hl = tid & 15;
        float4 s1 = ((const float4*)sWRx)[hl];
        float4 s2 = ((const float4*)sWx)[hl];
        #pragma unroll
        for (int mo = 0; mo < 8; mo++) {
            const int n0 = g + 16 * (4 * mo);
            float4 w0 = ((const float4*)(WLt + (size_t)(n0 +  0) * KK))[hl];
            float4 w1 = ((const float4*)(WLt + (size_t)(n0 + 16) * KK))[hl];
            float4 w2 = ((const float4*)(WLt + (size_t)(n0 + 32) * KK))[hl];
            float4 w3 = ((const float4*)(WLt + (size_t)(n0 + 48) * KK))[hl];
            float a1_0 = w0.x*s1.x + w0.y*s1.y + w0.z*s1.z + w0.w*s1.w;
            float a1_1 = w1.x*s1.x + w1.y*s1.y + w1.z*s1.z + w1.w*s1.w;
            float a1_2 = w2.x*s1.x + w2.y*s1.y + w2.z*s1.z + w2.w*s1.w;
            float a1_3 = w3.x*s1.x + w3.y*s1.y + w3.z*s1.z + w3.w*s1.w;
            float a2_0 = w0.x*s2.x + w0.y*s2.y + w0.z*s2.z + w0.w*s2.w;
            float a2_1 = w1.x*s2.x + w1.y*s2.y + w1.z*s2.z + w1.w*s2.w;
            float a2_2 = w2.x*s2.x + w2.y*s2.y + w2.z*s2.z + w2.w*s2.w;
            float a2_3 = w3.x*s2.x + w3.y*s2.y + w3.z*s2.z + w3.w*s2.w;
            #pragma unroll
            for (int o = 8; o > 0; o >>= 1) {
                a1_0 += __shfl_xor_sync(0xFFFFFFFFu, a1_0, o);
                a1_1 += __shfl_xor_sync(0xFFFFFFFFu, a1_1, o);
                a1_2 += __shfl_xor_sync(0xFFFFFFFFu, a1_2, o);
                a1_3 += __shfl_xor_sync(0xFFFFFFFFu, a1_3, o);
                a2_0 += __shfl_xor_sync(0xFFFFFFFFu, a2_0, o);
                a2_1 += __shfl_xor_sync(0xFFFFFFFFu, a2_1, o);
                a2_2 += __shfl_xor_sync(0xFFFFFFFFu, a2_2, o);
                a2_3 += __shfl_xor_sync(0xFFFFFFFFu, a2_3, o);
            }
            if (hl == 0) {
                sAcc1[n0 +  0] = a1_0;  sAcc2[n0 +  0] = a2_0;
                sAcc1[n0 + 16] = a1_1;  sAcc2[n0 + 16] = a2_1;
                sAcc1[n0 + 32] = a1_2;  sAcc2[n0 + 32] = a2_2;
                sAcc1[n0 + 48] = a1_3;  sAcc2[n0 + 48] = a2_3;
            }
        }
    }
    __syncthreads();

    // ---- Epilogue: threads 0-127 -> dWL, 128-255 -> v_next ----
    if (tid < 128) {
        float4 a = ((const float4*)sAcc1)[tid];
        float4 t = ((const float4*)svB)[tid];
        float4 o;
        o.x = G_CONST * t.x - a.x;
        o.y = G_CONST * t.y - a.y;
        o.z = G_CONST * t.z - a.z;
        o.w = G_CONST * t.w - a.w;
        ((float4*)dWLrow)[tid] = o;
    } else {
        const int i = tid - 128;
        float4 a = ((const float4*)sAcc2)[i];
        float4 o;
        o.x = tanhf(a.x); o.y = tanhf(a.y);
        o.z = tanhf(a.z); o.w = tanhf(a.w);
        ((float4*)(out_vnext + (size_t)b * NN))[i] = o;
    }
}

extern "C" void kernel_launch(void* const* d_in, const int* in_sizes, int n_in,
                              void* d_out, int out_size) {
    const float* WL    = (const float*)d_in[0];
    const float* WR    = (const float*)d_in[1];
    const float* v_tm1 = (const float*)d_in[2];
    const float* v_t   = (const float*)d_in[3];
    const int*   ac    = (const int*)d_in[4];
    const int*   pcm   = (const int*)d_in[5];
    float* out = (float*)d_out;

    dim3 grid(BB, PP);
    ghu_kernel<<<grid, THREADS>>>(WL, WR, v_tm1, v_t, ac, pcm, out);
}

// round 15
// speedup vs baseline: 1.1663x; 1.1663x over previous
#include <cuda_runtime.h>

#define PP 8
#define BB 256
#define NN 512
#define KK 64
#define THREADS 128

// n = N*rho^2 = 510.976512 ; g = 0.5*(log(1+rho)-log(1-rho))/rho
#define G_CONST  3.8040054350965846f
#define INV_N    0.00195703687008f

__global__ __launch_bounds__(THREADS, 8)
void ghu_kernel(const float* __restrict__ WL,
                const float* __restrict__ WR,
                const float* __restrict__ v_tm1,
                const float* __restrict__ v_t,
                const int*   __restrict__ ac_idx,
                const int*   __restrict__ pc_mask,
                float* __restrict__ out) {
    const int b = blockIdx.x;
    const int p = blockIdx.y;
    const int tid  = threadIdx.x;
    const int warp = tid >> 5;   // 0..3
    const int lane = tid & 31;

    const bool sel = (ac_idx[b] == p);
    const bool msk = (pc_mask[b * PP + p] != 0);

    float* out_vnext = out;                                    // [B,N]
    float* out_dWL   = out + (size_t)BB * NN;                  // [P,B,N,1]
    float* out_dWR   = out_dWL + (size_t)PP * BB * NN;         // [P,B,1,N]
    float* dWLrow = out_dWL + ((size_t)p * BB + b) * NN;
    float* dWRrow = out_dWR + ((size_t)p * BB + b) * NN;
    const float* vtm1_row = v_tm1 + (size_t)b * NN;
    const float* vt_row   = v_t   + (size_t)b * NN;

    // ---- dWR needs no weight data: one float4 per thread (128 total) ----
    {
        float4 vv = ((const float4*)vtm1_row)[tid];
        float4 o;
        if (msk) { o.x = vv.x * INV_N; o.y = vv.y * INV_N;
                   o.z = vv.z * INV_N; o.w = vv.w * INV_N; }
        else     { o = make_float4(0.f, 0.f, 0.f, 0.f); }
        ((float4*)dWRrow)[tid] = o;
    }

    // Light tiles: zero dWL, done. No weight reads.
    if (!msk && !sel) {
        ((float4*)dWLrow)[tid] = make_float4(0.f, 0.f, 0.f, 0.f);
        return;
    }

    __shared__ __align__(16) float svA[NN];     // dot vector (v_tm1 or v_t)
    __shared__ __align__(16) float svB[NN];     // second vector (full path)
    __shared__ __align__(16) float sWRx[KK];
    __shared__ __align__(16) float sWx[KK];
    __shared__ __align__(16) float sAcc1[NN];
    __shared__ __align__(16) float sAcc2[NN];

    const size_t tileOff = ((size_t)p * BB + b) * (size_t)(NN * KK);
    const float* WRt = WR + tileOff;   // [K, N], N contiguous
    const float* WLt = WL + tileOff;   // [N, K], K contiguous

    if (msk != sel) {
        // ================= SINGLE-DOT PATH (~90% of heavy tiles) ==========
        const float* vrow = msk ? vtm1_row : vt_row;
        ((float4*)svA)[tid] = ((const float4*)vrow)[tid];
        __syncthreads();

        // ---- Phase A: warp w owns WR k-rows [16w..16w+15], 2 batches of 8.
        {
            const float* base = WRt + (size_t)(16 * warp) * NN;
            #pragma unroll
            for (int bt = 0; bt < 2; bt++) {
                float acc[8] = {0.f,0.f,0.f,0.f,0.f,0.f,0.f,0.f};
                #pragma unroll
                for (int j = 0; j < 4; j++) {
                    const int idx = lane + 32 * j;
                    const int vb  = 4 * idx;
                    float4 w[8];
                    #pragma unroll
                    for (int r = 0; r < 8; r++)
                        w[r] = ((const float4*)(base + (8 * bt + r) * NN))[idx];
                    const float u0 = svA[vb + 0], u1 = svA[vb + 1];
                    const float u2 = svA[vb + 2], u3 = svA[vb + 3];
                    #pragma unroll
                    for (int r = 0; r < 8; r++)
                        acc[r] = fmaf(w[r].x, u0, fmaf(w[r].y, u1,
                                 fmaf(w[r].z, u2, fmaf(w[r].w, u3, acc[r]))));
                }
                #pragma unroll
                for (int o = 16; o > 0; o >>= 1)
                    #pragma unroll
                    for (int r = 0; r < 8; r++)
                        acc[r] += __shfl_xor_sync(0xFFFFFFFFu, acc[r], o);
                if (lane == 0)
                    #pragma unroll
                    for (int r = 0; r < 8; r++)
                        sWRx[16 * warp + 8 * bt + r] = acc[r];
            }
        }
        __syncthreads();

        // ---- Phase B: 16-lane group g (0..7) owns WL rows n = g + 8m ----
        {
            const int g  = tid >> 4;
            const int hl = tid & 15;
            const float4 s1 = ((const float4*)sWRx)[hl];
            const float4* lb = (const float4*)(WLt + (size_t)g * KK) + hl;
            #pragma unroll
            for (int bt = 0; bt < 8; bt++) {
                float4 w[8];
                #pragma unroll
                for (int r = 0; r < 8; r++)
                    w[r] = lb[(8 * bt + r) * 128];   // 8*KK floats apart
                float a[8];
                #pragma unroll
                for (int r = 0; r < 8; r++)
                    a[r] = w[r].x*s1.x + w[r].y*s1.y + w[r].z*s1.z + w[r].w*s1.w;
                #pragma unroll
                for (int o = 8; o > 0; o >>= 1)
                    #pragma unroll
                    for (int r = 0; r < 8; r++)
                        a[r] += __shfl_xor_sync(0xFFFFFFFFu, a[r], o, 16);
                if (hl == 0)
                    #pragma unroll
                    for (int r = 0; r < 8; r++)
                        sAcc1[g + 8 * (8 * bt + r)] = a[r];
            }
        }
        __syncthreads();

        // ---- Epilogue (128 threads = 128 float4 = 512 floats) ----
        if (msk) {
            float4 a = ((const float4*)sAcc1)[tid];
            float4 t = ((const float4*)vt_row)[tid];
            float4 o;
            o.x = G_CONST * t.x - a.x;
            o.y = G_CONST * t.y - a.y;
            o.z = G_CONST * t.z - a.z;
            o.w = G_CONST * t.w - a.w;
            ((float4*)dWLrow)[tid] = o;
        } else {
            ((float4*)dWLrow)[tid] = make_float4(0.f, 0.f, 0.f, 0.f);
            float4 a = ((const float4*)sAcc1)[tid];
            float4 o;
            o.x = tanhf(a.x); o.y = tanhf(a.y);
            o.z = tanhf(a.z); o.w = tanhf(a.w);
            ((float4*)(out_vnext + (size_t)b * NN))[tid] = o;
        }
        return;
    }

    // ================= FULL DUAL-DOT PATH (msk && sel, ~6%) ===============
    ((float4*)svA)[tid] = ((const float4*)vtm1_row)[tid];
    ((float4*)svB)[tid] = ((const float4*)vt_row)[tid];
    __syncthreads();

    // ---- Phase A: warp owns k-rows [16w..16w+15], 4 batches of 4 (MLP 4).
    {
        const float* base = WRt + (size_t)(16 * warp) * NN;
        #pragma unroll
        for (int rb = 0; rb < 4; rb++) {
            float a1[4] = {0.f, 0.f, 0.f, 0.f};
            float a2[4] = {0.f, 0.f, 0.f, 0.f};
            #pragma unroll
            for (int j = 0; j < 4; j++) {
                const int idx  = lane + 32 * j;
                const int vb   = 4 * idx;
                float4 w[4];
                #pragma unroll
                for (int r = 0; r < 4; r++)
                    w[r] = ((const float4*)(base + (4 * rb + r) * NN))[idx];
                float u0 = svA[vb + 0], u1 = svA[vb + 1];
                float u2 = svA[vb + 2], u3 = svA[vb + 3];
                float t0 = svB[vb + 0], t1 = svB[vb + 1];
                float t2 = svB[vb + 2], t3 = svB[vb + 3];
                #pragma unroll
                for (int r = 0; r < 4; r++) {
                    a1[r] = fmaf(w[r].x,u0,fmaf(w[r].y,u1,fmaf(w[r].z,u2,fmaf(w[r].w,u3,a1[r]))));
                    a2[r] = fmaf(w[r].x,t0,fmaf(w[r].y,t1,fmaf(w[r].z,t2,fmaf(w[r].w,t3,a2[r]))));
                }
            }
            #pragma unroll
            for (int o = 16; o > 0; o >>= 1) {
                #pragma unroll
                for (int r = 0; r < 4; r++) {
                    a1[r] += __shfl_xor_sync(0xFFFFFFFFu, a1[r], o);
                    a2[r] += __shfl_xor_sync(0xFFFFFFFFu, a2[r], o);
                }
            }
            if (lane == 0) {
                #pragma unroll
                for (int r = 0; r < 4; r++) {
                    sWRx[16 * warp + 4 * rb + r] = a1[r];
                    sWx [16 * warp + 4 * rb + r] = a2[r];
                }
            }
        }
    }
    __syncthreads();

    // ---- Phase B: group g (0..7) owns rows n = g + 8m, 4 rows per pass.
    {
        const int g  = tid >> 4;
        const int hl = tid & 15;
        float4 s1 = ((const float4*)sWRx)[hl];
        float4 s2 = ((const float4*)sWx)[hl];
        const float4* lb = (const float4*)(WLt + (size_t)g * KK) + hl;
        #pragma unroll
        for (int mo = 0; mo < 16; mo++) {
            float4 w[4];
            #pragma unroll
            for (int r = 0; r < 4; r++)
                w[r] = lb[(4 * mo + r) * 128];
            float a1[4], a2[4];
            #pragma unroll
            for (int r = 0; r < 4; r++) {
                a1[r] = w[r].x*s1.x + w[r].y*s1.y + w[r].z*s1.z + w[r].w*s1.w;
                a2[r] = w[r].x*s2.x + w[r].y*s2.y + w[r].z*s2.z + w[r].w*s2.w;
            }
            #pragma unroll
            for (int o = 8; o > 0; o >>= 1) {
                #pragma unroll
                for (int r = 0; r < 4; r++) {
                    a1[r] += __shfl_xor_sync(0xFFFFFFFFu, a1[r], o, 16);
                    a2[r] += __shfl_xor_sync(0xFFFFFFFFu, a2[r], o, 16);
                }
            }
            if (hl == 0) {
                #pragma unroll
                for (int r = 0; r < 4; r++) {
                    sAcc1[g + 8 * (4 * mo + r)] = a1[r];
                    sAcc2[g + 8 * (4 * mo + r)] = a2[r];
                }
            }
        }
    }
    __syncthreads();

    // ---- Epilogue: both outputs, 128 threads each ----
    {
        float4 a = ((const float4*)sAcc1)[tid];
        float4 t = ((const float4*)svB)[tid];
        float4 o;
        o.x = G_CONST * t.x - a.x;
        o.y = G_CONST * t.y - a.y;
        o.z = G_CONST * t.z - a.z;
        o.w = G_CONST * t.w - a.w;
        ((float4*)dWLrow)[tid] = o;

        float4 a2 = ((const float4*)sAcc2)[tid];
        float4 o2;
        o2.x = tanhf(a2.x); o2.y = tanhf(a2.y);
        o2.z = tanhf(a2.z); o2.w = tanhf(a2.w);
        ((float4*)(out_vnext + (size_t)b * NN))[tid] = o2;
    }
}

extern "C" void kernel_launch(void* const* d_in, const int* in_sizes, int n_in,
                              void* d_out, int out_size) {
    const float* WL    = (const float*)d_in[0];
    const float* WR    = (const float*)d_in[1];
    const float* v_tm1 = (const float*)d_in[2];
    const float* v_t   = (const float*)d_in[3];
    const int*   ac    = (const int*)d_in[4];
    const int*   pcm   = (const int*)d_in[5];
    float* out = (float*)d_out;

    dim3 grid(BB, PP);
    ghu_kernel<<<grid, THREADS>>>(WL, WR, v_tm1, v_t, ac, pcm, out);
}

// round 16
// speedup vs baseline: 1.2532x; 1.0746x over previous
#include <cuda_runtime.h>

#define PP 8
#define BB 256
#define NN 512
#define KK 64
#define THREADS 256

// n = N*rho^2 = 510.976512 ; g = 0.5*(log(1+rho)-log(1-rho))/rho
#define G_CONST  3.8040054350965846f
#define INV_N    0.00195703687008f

__global__ __launch_bounds__(THREADS, 4)
void ghu_kernel(const float* __restrict__ WL,
                const float* __restrict__ WR,
                const float* __restrict__ v_tm1,
                const float* __restrict__ v_t,
                const int*   __restrict__ ac_idx,
                const int*   __restrict__ pc_mask,
                float* __restrict__ out) {
    const int b = blockIdx.x;
    const int p = blockIdx.y;
    const int tid  = threadIdx.x;
    const int warp = tid >> 5;
    const int lane = tid & 31;

    const bool sel = (ac_idx[b] == p);
    const bool msk = (pc_mask[b * PP + p] != 0);

    float* out_vnext = out;                                    // [B,N]
    float* out_dWL   = out + (size_t)BB * NN;                  // [P,B,N,1]
    float* out_dWR   = out_dWL + (size_t)PP * BB * NN;         // [P,B,1,N]
    float* dWLrow = out_dWL + ((size_t)p * BB + b) * NN;
    float* dWRrow = out_dWR + ((size_t)p * BB + b) * NN;
    const float* vtm1_row = v_tm1 + (size_t)b * NN;
    const float* vt_row   = v_t   + (size_t)b * NN;

    // Light tiles: outputs only, no weight reads.
    if (!msk && !sel) {
        if (tid < NN / 4) {
            ((float4*)dWRrow)[tid] = make_float4(0.f, 0.f, 0.f, 0.f);
            ((float4*)dWLrow)[tid] = make_float4(0.f, 0.f, 0.f, 0.f);
        }
        return;
    }

    // Heavy tiles: dWR is deferred to the epilogue so the weight-load
    // stream starts immediately.
    __shared__ __align__(16) float svA[NN];     // dot vector (v_tm1 or v_t)
    __shared__ __align__(16) float svB[NN];     // second vector (full path)
    __shared__ __align__(16) float sWRx[KK];
    __shared__ __align__(16) float sWx[KK];
    __shared__ __align__(16) float sAcc1[NN];
    __shared__ __align__(16) float sAcc2[NN];

    const size_t tileOff = ((size_t)p * BB + b) * (size_t)(NN * KK);
    const float* WRt = WR + tileOff;   // [K, N], N contiguous
    const float* WLt = WL + tileOff;   // [N, K], K contiguous

    if (msk != sel) {
        // ================= SINGLE-DOT PATH (~90% of heavy tiles) ==========
        const float* vrow = msk ? vtm1_row : vt_row;
        if (tid < NN / 4)
            ((float4*)svA)[tid] = ((const float4*)vrow)[tid];
        __syncthreads();

        // ---- Phase A: warp w owns WR k-rows [8w .. 8w+7], one batch ----
        {
            const float* base = WRt + (size_t)(8 * warp) * NN;
            float acc[8] = {0.f,0.f,0.f,0.f,0.f,0.f,0.f,0.f};
            #pragma unroll
            for (int j = 0; j < 4; j++) {
                const int idx = lane + 32 * j;
                const int vb  = 4 * idx;
                float4 w[8];
                #pragma unroll
                for (int r = 0; r < 8; r++)
                    w[r] = ((const float4*)(base + r * NN))[idx];
                const float u0 = svA[vb + 0], u1 = svA[vb + 1];
                const float u2 = svA[vb + 2], u3 = svA[vb + 3];
                #pragma unroll
                for (int r = 0; r < 8; r++)
                    acc[r] = fmaf(w[r].x, u0, fmaf(w[r].y, u1,
                             fmaf(w[r].z, u2, fmaf(w[r].w, u3, acc[r]))));
            }
            #pragma unroll
            for (int o = 16; o > 0; o >>= 1)
                #pragma unroll
                for (int r = 0; r < 8; r++)
                    acc[r] += __shfl_xor_sync(0xFFFFFFFFu, acc[r], o);
            if (lane == 0)
                #pragma unroll
                for (int r = 0; r < 8; r++)
                    sWRx[8 * warp + r] = acc[r];
        }

        // ---- Cross-barrier preload: phase B batch 0 loads depend only on
        // WLt, not sWRx. Issue them BEFORE the barrier so DRAM requests are
        // in flight while the barrier drains (kills the post-barrier cold
        // ~590-cycle bubble).
        const int g  = tid >> 4;
        const int hl = tid & 15;
        const float4* lb = (const float4*)(WLt + (size_t)g * KK) + hl;
        float4 wpre[8];
        #pragma unroll
        for (int r = 0; r < 8; r++)
            wpre[r] = lb[r * 256];   // rows g + 16r
        __syncthreads();

        // ---- Phase B: 16-lane group g owns WL rows n = g + 16m ----
        {
            const float4 s1 = ((const float4*)sWRx)[hl];
            // batch 0 from preloaded registers
            {
                float a[8];
                #pragma unroll
                for (int r = 0; r < 8; r++)
                    a[r] = wpre[r].x*s1.x + wpre[r].y*s1.y
                         + wpre[r].z*s1.z + wpre[r].w*s1.w;
                #pragma unroll
                for (int o = 8; o > 0; o >>= 1)
                    #pragma unroll
                    for (int r = 0; r < 8; r++)
                        a[r] += __shfl_xor_sync(0xFFFFFFFFu, a[r], o, 16);
                if (hl == 0)
                    #pragma unroll
                    for (int r = 0; r < 8; r++)
                        sAcc1[g + 16 * r] = a[r];
            }
            // batches 1..3 as before
            #pragma unroll
            for (int bt = 1; bt < 4; bt++) {
                float4 w[8];
                #pragma unroll
                for (int r = 0; r < 8; r++)
                    w[r] = lb[(8 * bt + r) * 256];
                float a[8];
                #pragma unroll
                for (int r = 0; r < 8; r++)
                    a[r] = w[r].x*s1.x + w[r].y*s1.y + w[r].z*s1.z + w[r].w*s1.w;
                #pragma unroll
                for (int o = 8; o > 0; o >>= 1)
                    #pragma unroll
                    for (int r = 0; r < 8; r++)
                        a[r] += __shfl_xor_sync(0xFFFFFFFFu, a[r], o, 16);
                if (hl == 0)
                    #pragma unroll
                    for (int r = 0; r < 8; r++)
                        sAcc1[g + 16 * (8 * bt + r)] = a[r];
            }
        }
        __syncthreads();

        // ---- Epilogue (dWR deferred here) ----
        if (msk) {
            // dWL = g*v_t - WLWRx ; dWR = v_tm1/n (svA holds v_tm1)
            if (tid < 128) {
                float4 a = ((const float4*)sAcc1)[tid];
                float4 t = ((const float4*)vt_row)[tid];
                float4 o;
                o.x = G_CONST * t.x - a.x;
                o.y = G_CONST * t.y - a.y;
                o.z = G_CONST * t.z - a.z;
                o.w = G_CONST * t.w - a.w;
                ((float4*)dWLrow)[tid] = o;
                float4 v = ((const float4*)svA)[tid];
                float4 w;
                w.x = v.x * INV_N; w.y = v.y * INV_N;
                w.z = v.z * INV_N; w.w = v.w * INV_N;
                ((float4*)dWRrow)[tid] = w;
            }
        } else {
            // sel only: dWL = 0 ; dWR = 0 ; v_next = tanh(acc)
            if (tid < 128) {
                ((float4*)dWLrow)[tid] = make_float4(0.f, 0.f, 0.f, 0.f);
                ((float4*)dWRrow)[tid] = make_float4(0.f, 0.f, 0.f, 0.f);
            } else {
                const int i = tid - 128;
                float4 a = ((const float4*)sAcc1)[i];
                float4 o;
                o.x = tanhf(a.x); o.y = tanhf(a.y);
                o.z = tanhf(a.z); o.w = tanhf(a.w);
                ((float4*)(out_vnext + (size_t)b * NN))[i] = o;
            }
        }
        return;
    }

    // ================= FULL DUAL-DOT PATH (msk && sel, ~6%) ===============
    if (tid < NN / 4) {
        ((float4*)svB)[tid] = ((const float4*)vt_row)[tid];
        ((float4*)svA)[tid] = ((const float4*)vtm1_row)[tid];
    }
    __syncthreads();

    // ---- Phase A: warp handles k = warp + 8*r, 4 rows per pass, 2 passes.
    #pragma unroll
    for (int rb = 0; rb < 2; rb++) {
        float a1[4] = {0.f, 0.f, 0.f, 0.f};
        float a2[4] = {0.f, 0.f, 0.f, 0.f};
        const float4* r0 = (const float4*)(WRt + (size_t)(warp + 8 * (4 * rb + 0)) * NN);
        const float4* r1 = (const float4*)(WRt + (size_t)(warp + 8 * (4 * rb + 1)) * NN);
        const float4* r2 = (const float4*)(WRt + (size_t)(warp + 8 * (4 * rb + 2)) * NN);
        const float4* r3 = (const float4*)(WRt + (size_t)(warp + 8 * (4 * rb + 3)) * NN);
        #pragma unroll
        for (int j = 0; j < 4; j++) {
            const int idx  = lane + 32 * j;
            const int base = 4 * idx;
            float4 w0 = r0[idx];
            float4 w1 = r1[idx];
            float4 w2 = r2[idx];
            float4 w3 = r3[idx];
            float u0 = svA[base + 0], u1 = svA[base + 1];
            float u2 = svA[base + 2], u3 = svA[base + 3];
            float t0 = svB[base + 0], t1 = svB[base + 1];
            float t2 = svB[base + 2], t3 = svB[base + 3];
            a1[0] = fmaf(w0.x,u0,fmaf(w0.y,u1,fmaf(w0.z,u2,fmaf(w0.w,u3,a1[0]))));
            a1[1] = fmaf(w1.x,u0,fmaf(w1.y,u1,fmaf(w1.z,u2,fmaf(w1.w,u3,a1[1]))));
            a1[2] = fmaf(w2.x,u0,fmaf(w2.y,u1,fmaf(w2.z,u2,fmaf(w2.w,u3,a1[2]))));
            a1[3] = fmaf(w3.x,u0,fmaf(w3.y,u1,fmaf(w3.z,u2,fmaf(w3.w,u3,a1[3]))));
            a2[0] = fmaf(w0.x,t0,fmaf(w0.y,t1,fmaf(w0.z,t2,fmaf(w0.w,t3,a2[0]))));
            a2[1] = fmaf(w1.x,t0,fmaf(w1.y,t1,fmaf(w1.z,t2,fmaf(w1.w,t3,a2[1]))));
            a2[2] = fmaf(w2.x,t0,fmaf(w2.y,t1,fmaf(w2.z,t2,fmaf(w2.w,t3,a2[2]))));
            a2[3] = fmaf(w3.x,t0,fmaf(w3.y,t1,fmaf(w3.z,t2,fmaf(w3.w,t3,a2[3]))));
        }
        #pragma unroll
        for (int o = 16; o > 0; o >>= 1) {
            #pragma unroll
            for (int r = 0; r < 4; r++) {
                a1[r] += __shfl_xor_sync(0xFFFFFFFFu, a1[r], o);
                a2[r] += __shfl_xor_sync(0xFFFFFFFFu, a2[r], o);
            }
        }
        if (lane == 0) {
            #pragma unroll
            for (int r = 0; r < 4; r++) {
                sWRx[warp + 8 * (4 * rb + r)] = a1[r];
                sWx [warp + 8 * (4 * rb + r)] = a2[r];
            }
        }
    }
    __syncthreads();

    // ---- Phase B: 16-lane group g owns rows n = g + 16*m, 4 rows per pass.
    {
        const int g  = tid >> 4;
        const int hl = tid & 15;
        float4 s1 = ((const float4*)sWRx)[hl];
        float4 s2 = ((const float4*)sWx)[hl];
        #pragma unroll
        for (int mo = 0; mo < 8; mo++) {
            const int n0 = g + 16 * (4 * mo);
            float4 w0 = ((const float4*)(WLt + (size_t)(n0 +  0) * KK))[hl];
            float4 w1 = ((const float4*)(WLt + (size_t)(n0 + 16) * KK))[hl];
            float4 w2 = ((const float4*)(WLt + (size_t)(n0 + 32) * KK))[hl];
            float4 w3 = ((const float4*)(WLt + (size_t)(n0 + 48) * KK))[hl];
            float a1_0 = w0.x*s1.x + w0.y*s1.y + w0.z*s1.z + w0.w*s1.w;
            float a1_1 = w1.x*s1.x + w1.y*s1.y + w1.z*s1.z + w1.w*s1.w;
            float a1_2 = w2.x*s1.x + w2.y*s1.y + w2.z*s1.z + w2.w*s1.w;
            float a1_3 = w3.x*s1.x + w3.y*s1.y + w3.z*s1.z + w3.w*s1.w;
            float a2_0 = w0.x*s2.x + w0.y*s2.y + w0.z*s2.z + w0.w*s2.w;
            float a2_1 = w1.x*s2.x + w1.y*s2.y + w1.z*s2.z + w1.w*s2.w;
            float a2_2 = w2.x*s2.x + w2.y*s2.y + w2.z*s2.z + w2.w*s2.w;
            float a2_3 = w3.x*s2.x + w3.y*s2.y + w3.z*s2.z + w3.w*s2.w;
            #pragma unroll
            for (int o = 8; o > 0; o >>= 1) {
                a1_0 += __shfl_xor_sync(0xFFFFFFFFu, a1_0, o);
                a1_1 += __shfl_xor_sync(0xFFFFFFFFu, a1_1, o);
                a1_2 += __shfl_xor_sync(0xFFFFFFFFu, a1_2, o);
                a1_3 += __shfl_xor_sync(0xFFFFFFFFu, a1_3, o);
                a2_0 += __shfl_xor_sync(0xFFFFFFFFu, a2_0, o);
                a2_1 += __shfl_xor_sync(0xFFFFFFFFu, a2_1, o);
                a2_2 += __shfl_xor_sync(0xFFFFFFFFu, a2_2, o);
                a2_3 += __shfl_xor_sync(0xFFFFFFFFu, a2_3, o);
            }
            if (hl == 0) {
                sAcc1[n0 +  0] = a1_0;  sAcc2[n0 +  0] = a2_0;
                sAcc1[n0 + 16] = a1_1;  sAcc2[n0 + 16] = a2_1;
                sAcc1[n0 + 32] = a1_2;  sAcc2[n0 + 32] = a2_2;
                sAcc1[n0 + 48] = a1_3;  sAcc2[n0 + 48] = a2_3;
            }
        }
    }
    __syncthreads();

    // ---- Epilogue: dWL + dWR on threads 0-127, v_next on 128-255 ----
    if (tid < 128) {
        float4 a = ((const float4*)sAcc1)[tid];
        float4 t = ((const float4*)svB)[tid];
        float4 o;
        o.x = G_CONST * t.x - a.x;
        o.y = G_CONST * t.y - a.y;
        o.z = G_CONST * t.z - a.z;
        o.w = G_CONST * t.w - a.w;
        ((float4*)dWLrow)[tid] = o;
        float4 v = ((const float4*)svA)[tid];
        float4 w;
        w.x = v.x * INV_N; w.y = v.y * INV_N;
        w.z = v.z * INV_N; w.w = v.w * INV_N;
        ((float4*)dWRrow)[tid] = w;
    } else {
        const int i = tid - 128;
        float4 a = ((const float4*)sAcc2)[i];
        float4 o;
        o.x = tanhf(a.x); o.y = tanhf(a.y);
        o.z = tanhf(a.z); o.w = tanhf(a.w);
        ((float4*)(out_vnext + (size_t)b * NN))[i] = o;
    }
}

extern "C" void kernel_launch(void* const* d_in, const int* in_sizes, int n_in,
                              void* d_out, int out_size) {
    const float* WL    = (const float*)d_in[0];
    const float* WR    = (const float*)d_in[1];
    const float* v_tm1 = (const float*)d_in[2];
    const float* v_t   = (const float*)d_in[3];
    const int*   ac    = (const int*)d_in[4];
    const int*   pcm   = (const int*)d_in[5];
    float* out = (float*)d_out;

    dim3 grid(BB, PP);
    ghu_kernel<<<grid, THREADS>>>(WL, WR, v_tm1, v_t, ac, pcm, out);
}

// round 17
// speedup vs baseline: 1.3225x; 1.0553x over previous
#include <cuda_runtime.h>

#define PP 8
#define BB 256
#define NN 512
#define KK 64
#define THREADS 256

// n = N*rho^2 = 510.976512 ; g = 0.5*(log(1+rho)-log(1-rho))/rho
#define G_CONST  3.8040054350965846f
#define INV_N    0.00195703687008f

// Read-once weight load: evict-first in L1/L2 (no reuse, don't pollute).
__device__ __forceinline__ float4 ldcs4(const float4* p) { return __ldcs(p); }
// Write-only output store: streaming policy.
__device__ __forceinline__ void stcs4(float4* p, float4 v) { __stcs(p, v); }

__global__ __launch_bounds__(THREADS, 4)
void ghu_kernel(const float* __restrict__ WL,
                const float* __restrict__ WR,
                const float* __restrict__ v_tm1,
                const float* __restrict__ v_t,
                const int*   __restrict__ ac_idx,
                const int*   __restrict__ pc_mask,
                float* __restrict__ out) {
    const int b = blockIdx.x;
    const int p = blockIdx.y;
    const int tid  = threadIdx.x;
    const int warp = tid >> 5;
    const int lane = tid & 31;

    const bool sel = (ac_idx[b] == p);
    const bool msk = (pc_mask[b * PP + p] != 0);

    float* out_vnext = out;                                    // [B,N]
    float* out_dWL   = out + (size_t)BB * NN;                  // [P,B,N,1]
    float* out_dWR   = out_dWL + (size_t)PP * BB * NN;         // [P,B,1,N]
    float* dWLrow = out_dWL + ((size_t)p * BB + b) * NN;
    float* dWRrow = out_dWR + ((size_t)p * BB + b) * NN;
    const float* vtm1_row = v_tm1 + (size_t)b * NN;
    const float* vt_row   = v_t   + (size_t)b * NN;

    // Light tiles: outputs only, no weight reads.
    if (!msk && !sel) {
        if (tid < NN / 4) {
            stcs4(((float4*)dWRrow) + tid, make_float4(0.f, 0.f, 0.f, 0.f));
            stcs4(((float4*)dWLrow) + tid, make_float4(0.f, 0.f, 0.f, 0.f));
        }
        return;
    }

    __shared__ __align__(16) float svA[NN];     // dot vector (v_tm1 or v_t)
    __shared__ __align__(16) float svB[NN];     // second vector (full path)
    __shared__ __align__(16) float sWRx[KK];
    __shared__ __align__(16) float sWx[KK];
    __shared__ __align__(16) float sAcc1[NN];
    __shared__ __align__(16) float sAcc2[NN];

    const size_t tileOff = ((size_t)p * BB + b) * (size_t)(NN * KK);
    const float* WRt = WR + tileOff;   // [K, N], N contiguous
    const float* WLt = WL + tileOff;   // [N, K], K contiguous

    if (msk != sel) {
        // ================= SINGLE-DOT PATH (~90% of heavy tiles) ==========
        const float* vrow = msk ? vtm1_row : vt_row;
        if (tid < NN / 4)
            ((float4*)svA)[tid] = ((const float4*)vrow)[tid];
        __syncthreads();

        // ---- Phase A: warp w owns WR k-rows [8w .. 8w+7], one batch ----
        {
            const float* base = WRt + (size_t)(8 * warp) * NN;
            float acc[8] = {0.f,0.f,0.f,0.f,0.f,0.f,0.f,0.f};
            #pragma unroll
            for (int j = 0; j < 4; j++) {
                const int idx = lane + 32 * j;
                const int vb  = 4 * idx;
                float4 w[8];
                #pragma unroll
                for (int r = 0; r < 8; r++)
                    w[r] = ldcs4(((const float4*)(base + r * NN)) + idx);
                const float u0 = svA[vb + 0], u1 = svA[vb + 1];
                const float u2 = svA[vb + 2], u3 = svA[vb + 3];
                #pragma unroll
                for (int r = 0; r < 8; r++)
                    acc[r] = fmaf(w[r].x, u0, fmaf(w[r].y, u1,
                             fmaf(w[r].z, u2, fmaf(w[r].w, u3, acc[r]))));
            }
            #pragma unroll
            for (int o = 16; o > 0; o >>= 1)
                #pragma unroll
                for (int r = 0; r < 8; r++)
                    acc[r] += __shfl_xor_sync(0xFFFFFFFFu, acc[r], o);
            if (lane == 0)
                #pragma unroll
                for (int r = 0; r < 8; r++)
                    sWRx[8 * warp + r] = acc[r];
        }

        // ---- Cross-barrier preload: phase B batch 0 depends only on WLt.
        const int g  = tid >> 4;
        const int hl = tid & 15;
        const float4* lb = (const float4*)(WLt + (size_t)g * KK) + hl;
        float4 wpre[8];
        #pragma unroll
        for (int r = 0; r < 8; r++)
            wpre[r] = ldcs4(lb + r * 256);   // rows g + 16r
        __syncthreads();

        // ---- Phase B: 16-lane group g owns WL rows n = g + 16m ----
        {
            const float4 s1 = ((const float4*)sWRx)[hl];
            {
                float a[8];
                #pragma unroll
                for (int r = 0; r < 8; r++)
                    a[r] = wpre[r].x*s1.x + wpre[r].y*s1.y
                         + wpre[r].z*s1.z + wpre[r].w*s1.w;
                #pragma unroll
                for (int o = 8; o > 0; o >>= 1)
                    #pragma unroll
                    for (int r = 0; r < 8; r++)
                        a[r] += __shfl_xor_sync(0xFFFFFFFFu, a[r], o, 16);
                if (hl == 0)
                    #pragma unroll
                    for (int r = 0; r < 8; r++)
                        sAcc1[g + 16 * r] = a[r];
            }
            #pragma unroll
            for (int bt = 1; bt < 4; bt++) {
                float4 w[8];
                #pragma unroll
                for (int r = 0; r < 8; r++)
                    w[r] = ldcs4(lb + (8 * bt + r) * 256);
                float a[8];
                #pragma unroll
                for (int r = 0; r < 8; r++)
                    a[r] = w[r].x*s1.x + w[r].y*s1.y + w[r].z*s1.z + w[r].w*s1.w;
                #pragma unroll
                for (int o = 8; o > 0; o >>= 1)
                    #pragma unroll
                    for (int r = 0; r < 8; r++)
                        a[r] += __shfl_xor_sync(0xFFFFFFFFu, a[r], o, 16);
                if (hl == 0)
                    #pragma unroll
                    for (int r = 0; r < 8; r++)
                        sAcc1[g + 16 * (8 * bt + r)] = a[r];
            }
        }
        __syncthreads();

        // ---- Epilogue (streaming stores) ----
        if (msk) {
            if (tid < 128) {
                float4 a = ((const float4*)sAcc1)[tid];
                float4 t = ((const float4*)vt_row)[tid];
                float4 o;
                o.x = G_CONST * t.x - a.x;
                o.y = G_CONST * t.y - a.y;
                o.z = G_CONST * t.z - a.z;
                o.w = G_CONST * t.w - a.w;
                stcs4(((float4*)dWLrow) + tid, o);
                float4 v = ((const float4*)svA)[tid];
                float4 w;
                w.x = v.x * INV_N; w.y = v.y * INV_N;
                w.z = v.z * INV_N; w.w = v.w * INV_N;
                stcs4(((float4*)dWRrow) + tid, w);
            }
        } else {
            if (tid < 128) {
                stcs4(((float4*)dWLrow) + tid, make_float4(0.f, 0.f, 0.f, 0.f));
                stcs4(((float4*)dWRrow) + tid, make_float4(0.f, 0.f, 0.f, 0.f));
            } else {
                const int i = tid - 128;
                float4 a = ((const float4*)sAcc1)[i];
                float4 o;
                o.x = tanhf(a.x); o.y = tanhf(a.y);
                o.z = tanhf(a.z); o.w = tanhf(a.w);
                stcs4(((float4*)(out_vnext + (size_t)b * NN)) + i, o);
            }
        }
        return;
    }

    // ================= FULL DUAL-DOT PATH (msk && sel, ~6%) ===============
    if (tid < NN / 4) {
        ((float4*)svB)[tid] = ((const float4*)vt_row)[tid];
        ((float4*)svA)[tid] = ((const float4*)vtm1_row)[tid];
    }
    __syncthreads();

    #pragma unroll
    for (int rb = 0; rb < 2; rb++) {
        float a1[4] = {0.f, 0.f, 0.f, 0.f};
        float a2[4] = {0.f, 0.f, 0.f, 0.f};
        const float4* r0 = (const float4*)(WRt + (size_t)(warp + 8 * (4 * rb + 0)) * NN);
        const float4* r1 = (const float4*)(WRt + (size_t)(warp + 8 * (4 * rb + 1)) * NN);
        const float4* r2 = (const float4*)(WRt + (size_t)(warp + 8 * (4 * rb + 2)) * NN);
        const float4* r3 = (const float4*)(WRt + (size_t)(warp + 8 * (4 * rb + 3)) * NN);
        #pragma unroll
        for (int j = 0; j < 4; j++) {
            const int idx  = lane + 32 * j;
            const int base = 4 * idx;
            float4 w0 = ldcs4(r0 + idx);
            float4 w1 = ldcs4(r1 + idx);
            float4 w2 = ldcs4(r2 + idx);
            float4 w3 = ldcs4(r3 + idx);
            float u0 = svA[base + 0], u1 = svA[base + 1];
            float u2 = svA[base + 2], u3 = svA[base + 3];
            float t0 = svB[base + 0], t1 = svB[base + 1];
            float t2 = svB[base + 2], t3 = svB[base + 3];
            a1[0] = fmaf(w0.x,u0,fmaf(w0.y,u1,fmaf(w0.z,u2,fmaf(w0.w,u3,a1[0]))));
            a1[1] = fmaf(w1.x,u0,fmaf(w1.y,u1,fmaf(w1.z,u2,fmaf(w1.w,u3,a1[1]))));
            a1[2] = fmaf(w2.x,u0,fmaf(w2.y,u1,fmaf(w2.z,u2,fmaf(w2.w,u3,a1[2]))));
            a1[3] = fmaf(w3.x,u0,fmaf(w3.y,u1,fmaf(w3.z,u2,fmaf(w3.w,u3,a1[3]))));
            a2[0] = fmaf(w0.x,t0,fmaf(w0.y,t1,fmaf(w0.z,t2,fmaf(w0.w,t3,a2[0]))));
            a2[1] = fmaf(w1.x,t0,fmaf(w1.y,t1,fmaf(w1.z,t2,fmaf(w1.w,t3,a2[1]))));
            a2[2] = fmaf(w2.x,t0,fmaf(w2.y,t1,fmaf(w2.z,t2,fmaf(w2.w,t3,a2[2]))));
            a2[3] = fmaf(w3.x,t0,fmaf(w3.y,t1,fmaf(w3.z,t2,fmaf(w3.w,t3,a2[3]))));
        }
        #pragma unroll
        for (int o = 16; o > 0; o >>= 1) {
            #pragma unroll
            for (int r = 0; r < 4; r++) {
                a1[r] += __shfl_xor_sync(0xFFFFFFFFu, a1[r], o);
                a2[r] += __shfl_xor_sync(0xFFFFFFFFu, a2[r], o);
            }
        }
        if (lane == 0) {
            #pragma unroll
            for (int r = 0; r < 4; r++) {
                sWRx[warp + 8 * (4 * rb + r)] = a1[r];
                sWx [warp + 8 * (4 * rb + r)] = a2[r];
            }
        }
    }
    __syncthreads();

    {
        const int g  = tid >> 4;
        const int hl = tid & 15;
        float4 s1 = ((const float4*)sWRx)[hl];
        float4 s2 = ((const float4*)sWx)[hl];
        #pragma unroll
        for (int mo = 0; mo < 8; mo++) {
            const int n0 = g + 16 * (4 * mo);
            float4 w0 = ldcs4(((const float4*)(WLt + (size_t)(n0 +  0) * KK)) + hl);
            float4 w1 = ldcs4(((const float4*)(WLt + (size_t)(n0 + 16) * KK)) + hl);
            float4 w2 = ldcs4(((const float4*)(WLt + (size_t)(n0 + 32) * KK)) + hl);
            float4 w3 = ldcs4(((const float4*)(WLt + (size_t)(n0 + 48) * KK)) + hl);
            float a1_0 = w0.x*s1.x + w0.y*s1.y + w0.z*s1.z + w0.w*s1.w;
            float a1_1 = w1.x*s1.x + w1.y*s1.y + w1.z*s1.z + w1.w*s1.w;
            float a1_2 = w2.x*s1.x + w2.y*s1.y + w2.z*s1.z + w2.w*s1.w;
            float a1_3 = w3.x*s1.x + w3.y*s1.y + w3.z*s1.z + w3.w*s1.w;
            float a2_0 = w0.x*s2.x + w0.y*s2.y + w0.z*s2.z + w0.w*s2.w;
            float a2_1 = w1.x*s2.x + w1.y*s2.y + w1.z*s2.z + w1.w*s2.w;
            float a2_2 = w2.x*s2.x + w2.y*s2.y + w2.z*s2.z + w2.w*s2.w;
            float a2_3 = w3.x*s2.x + w3.y*s2.y + w3.z*s2.z + w3.w*s2.w;
            #pragma unroll
            for (int o = 8; o > 0; o >>= 1) {
                a1_0 += __shfl_xor_sync(0xFFFFFFFFu, a1_0, o);
                a1_1 += __shfl_xor_sync(0xFFFFFFFFu, a1_1, o);
                a1_2 += __shfl_xor_sync(0xFFFFFFFFu, a1_2, o);
                a1_3 += __shfl_xor_sync(0xFFFFFFFFu, a1_3, o);
                a2_0 += __shfl_xor_sync(0xFFFFFFFFu, a2_0, o);
                a2_1 += __shfl_xor_sync(0xFFFFFFFFu, a2_1, o);
                a2_2 += __shfl_xor_sync(0xFFFFFFFFu, a2_2, o);
                a2_3 += __shfl_xor_sync(0xFFFFFFFFu, a2_3, o);
            }
            if (hl == 0) {
                sAcc1[n0 +  0] = a1_0;  sAcc2[n0 +  0] = a2_0;
                sAcc1[n0 + 16] = a1_1;  sAcc2[n0 + 16] = a2_1;
                sAcc1[n0 + 32] = a1_2;  sAcc2[n0 + 32] = a2_2;
                sAcc1[n0 + 48] = a1_3;  sAcc2[n0 + 48] = a2_3;
            }
        }
    }
    __syncthreads();

    if (tid < 128) {
        float4 a = ((const float4*)sAcc1)[tid];
        float4 t = ((const float4*)svB)[tid];
        float4 o;
        o.x = G_CONST * t.x - a.x;
        o.y = G_CONST * t.y - a.y;
        o.z = G_CONST * t.z - a.z;
        o.w = G_CONST * t.w - a.w;
        stcs4(((float4*)dWLrow) + tid, o);
        float4 v = ((const float4*)svA)[tid];
        float4 w;
        w.x = v.x * INV_N; w.y = v.y * INV_N;
        w.z = v.z * INV_N; w.w = v.w * INV_N;
        stcs4(((float4*)dWRrow) + tid, w);
    } else {
        const int i = tid - 128;
        float4 a = ((const float4*)sAcc2)[i];
        float4 o;
        o.x = tanhf(a.x); o.y = tanhf(a.y);
        o.z = tanhf(a.z); o.w = tanhf(a.w);
        stcs4(((float4*)(out_vnext + (size_t)b * NN)) + i, o);
    }
}

extern "C" void kernel_launch(void* const* d_in, const int* in_sizes, int n_in,
                              void* d_out, int out_size) {
    const float* WL    = (const float*)d_in[0];
    const float* WR    = (const float*)d_in[1];
    const float* v_tm1 = (const float*)d_in[2];
    const float* v_t   = (const float*)d_in[3];
    const int*   ac    = (const int*)d_in[4];
    const int*   pcm   = (const int*)d_in[5];
    float* out = (float*)d_out;

    dim3 grid(BB, PP);
    ghu_kernel<<<grid, THREADS>>>(WL, WR, v_tm1, v_t, ac, pcm, out);
}